// round 6
// baseline (speedup 1.0000x reference)
#include <cuda_runtime.h>
#include <math.h>

// Problem constants (fixed shapes from setup_inputs)
#define BB    4
#define NN    16384
#define MM    1024
#define DD    3
#define CC    64
#define COP   64
#define COUT  128
#define KK    32
#define R2    0.25f
#define JIN   67          // D + C
#define JPAD  68          // padded to multiple of 4 (68*4B = 272B = 17*16B, float4-clean)

__global__ __launch_bounds__(128, 4)
void pointnet_sampler_kernel(
    const float* __restrict__ positions,   // (B, N, 3)
    const float* __restrict__ features,    // (B, N, 64)
    const float* __restrict__ centers,     // (B, M, 3)
    const float* __restrict__ distances,   // (B, M, N) squared distances
    const float* __restrict__ W_op,        // (67, 64)
    const float* __restrict__ b_op,        // (64,)
    const float* __restrict__ W_agg,       // (64, 128)
    const float* __restrict__ b_agg,       // (128,)
    float* __restrict__ out)               // (B, M, 128)
{
    const int bm   = blockIdx.x;           // 0 .. B*M-1
    const int b    = bm >> 10;             // / 1024
    const int tid  = threadIdx.x;
    const int lane = tid & 31;
    const int wid  = tid >> 5;
    const int c    = tid & 63;             // W_op output channel this thread owns

    __shared__ int   s_idx[KK];
    __shared__ int   s_count;
    __shared__ __align__(16) float s_in[KK][JPAD];  // [rel(3) | feat(64) | 0]
    __shared__ float s_pp[2][COP];                   // partial max from each K-half

    // ---- All threads: prefetch W_op column into registers (overlaps ball query) ----
    float w[JPAD];
    #pragma unroll
    for (int j = 0; j < JIN; j++) w[j] = W_op[j * COP + c];
    w[JIN] = 0.0f;
    const float bias = b_op[c];

    // ---- Warp 0: ball query with early exit (first KK hits in original order) ----
    if (wid == 0) {
        const float* drow = distances + ((size_t)bm) * NN;
        int count = 0;
        for (int j0 = 0; j0 < NN && count < KK; j0 += 32) {
            const int j = j0 + lane;                 // NN % 32 == 0, always in range
            const bool pred = (drow[j] < R2);
            const unsigned mask = __ballot_sync(0xFFFFFFFFu, pred);
            if (pred) {
                const int rank = count + __popc(mask & ((1u << lane) - 1u));
                if (rank < KK) s_idx[rank] = j;
            }
            count += __popc(mask);                   // uniform across the warp
        }
        if (count > KK) count = KK;
        if (lane == 0) s_count = count;
        for (int k = count + lane; k < KK; k += 32) s_idx[k] = 0;  // value unused
    }
    __syncthreads();

    const int cnt = s_count;

    // ---- Cooperative gather: rel-pos + features into smem ----
    const float* ctr = centers + ((size_t)bm) * DD;
    for (int e = tid; e < KK * JPAD; e += 128) {
        const int k = e / JPAD;
        const int j = e - k * JPAD;
        float v = 0.0f;
        if (k < cnt) {
            const int idx = s_idx[k];
            if (j < DD) {
                v = positions[((size_t)b * NN + idx) * DD + j] - ctr[j];
            } else if (j < JIN) {
                v = features[((size_t)b * NN + idx) * CC + (j - DD)];
            }
        }
        s_in[k][j] = v;
    }
    __syncthreads();

    // ---- NeighborOperator + max-pool: each thread = one channel, half the K slots ----
    const int half = tid >> 6;                 // 0 or 1
    const int k0   = half * (KK / 2);
    float pooled = -INFINITY;
    for (int k = k0; k < k0 + KK / 2; k++) {
        const float4* in4 = reinterpret_cast<const float4*>(&s_in[k][0]);
        float a0 = 0.0f, a1 = 0.0f;            // dual accumulators: break FFMA RAW chain
        #pragma unroll
        for (int q = 0; q < JPAD / 4; q++) {   // 17 x LDS.128 (warp-broadcast, conflict-free)
            const float4 v = in4[q];
            a0 = fmaf(v.x, w[4 * q + 0], a0);
            a1 = fmaf(v.y, w[4 * q + 1], a1);
            a0 = fmaf(v.z, w[4 * q + 2], a0);
            a1 = fmaf(v.w, w[4 * q + 3], a1);
        }
        // invalid slots contribute 0.0 to the max (matches jnp.where(mask, f, 0))
        const float val = (k < cnt) ? (a0 + a1 + bias) : 0.0f;
        pooled = fmaxf(pooled, val);
    }
    s_pp[half][c] = pooled;
    __syncthreads();

    // ---- Aggregation GEMM (64 -> 128) + ReLU: each thread = one output channel ----
    float acc = b_agg[tid];
    #pragma unroll 8
    for (int cc = 0; cc < COP; cc++) {
        const float p = fmaxf(s_pp[0][cc], s_pp[1][cc]);
        acc = fmaf(p, W_agg[cc * COUT + tid], acc);
    }
    out[((size_t)bm) * COUT + tid] = fmaxf(acc, 0.0f);
}

extern "C" void kernel_launch(void* const* d_in, const int* in_sizes, int n_in,
                              void* d_out, int out_size)
{
    const float* positions = (const float*)d_in[0];
    const float* features  = (const float*)d_in[1];
    const float* centers   = (const float*)d_in[2];
    const float* distances = (const float*)d_in[3];
    const float* W_op      = (const float*)d_in[4];
    const float* b_op      = (const float*)d_in[5];
    const float* W_agg     = (const float*)d_in[6];
    const float* b_agg     = (const float*)d_in[7];
    float*       out       = (float*)d_out;

    pointnet_sampler_kernel<<<BB * MM, 128>>>(
        positions, features, centers, distances,
        W_op, b_op, W_agg, b_agg, out);
}